// round 1
// baseline (speedup 1.0000x reference)
#include <cuda_runtime.h>
#include <math.h>

// ---------------- problem constants ----------------
#define NP 16384            // H*W per batch
#define NB 2                // batch
#define PL (NB * NP)        // floats per channel across batch

// scratch layout (channel counts)
// F 192 | X1 192 | MT 192 | OUTD 384 | ATTIN 192 | QKV0 576 | QKV 576 |
// OUTA 192 | XMID 192 | X2L 192 | FM 576 | XIN 1152 | DW 1152 | MT2 576 |
// OUT2 1152 | GX 576   => 8064 channels
#define OFF_F      ((size_t)0)
#define OFF_X1     (OFF_F     + (size_t)192  * PL)
#define OFF_MT     (OFF_X1    + (size_t)192  * PL)
#define OFF_OUTD   (OFF_MT    + (size_t)192  * PL)
#define OFF_ATTIN  (OFF_OUTD  + (size_t)384  * PL)
#define OFF_QKV0   (OFF_ATTIN + (size_t)192  * PL)
#define OFF_QKV    (OFF_QKV0  + (size_t)576  * PL)
#define OFF_OUTA   (OFF_QKV   + (size_t)576  * PL)
#define OFF_XMID   (OFF_OUTA  + (size_t)192  * PL)
#define OFF_X2L    (OFF_XMID  + (size_t)192  * PL)
#define OFF_FM     (OFF_X2L   + (size_t)192  * PL)
#define OFF_XIN    (OFF_FM    + (size_t)576  * PL)
#define OFF_DW     (OFF_XIN   + (size_t)1152 * PL)
#define OFF_MT2    (OFF_DW    + (size_t)1152 * PL)
#define OFF_OUT2   (OFF_MT2   + (size_t)576  * PL)
#define OFF_GX     (OFF_OUT2  + (size_t)1152 * PL)
#define OFF_NRM    (OFF_GX    + (size_t)576  * PL)   // 768 floats
#define OFF_S      (OFF_NRM   + (size_t)1024)        // 16 * 12288 partials
#define KSPLIT 16
#define SCRATCH_FLOATS (OFF_S + (size_t)KSPLIT * 12288)

__device__ float g_scratch[SCRATCH_FLOATS];

// ---------------- LayerNorm over channel dim ----------------
__global__ void ln_kernel(const float* __restrict__ in, const float* __restrict__ g,
                          const float* __restrict__ be, float* __restrict__ out, int C)
{
    int b = blockIdx.y;
    int p = blockIdx.x * 256 + threadIdx.x;
    const float* ib = in + (size_t)b * C * NP + p;
    float s = 0.f, ss = 0.f;
    for (int c = 0; c < C; c++) {
        float v = ib[(size_t)c * NP];
        s += v; ss += v * v;
    }
    float mu = s / C;
    float var = ss / C - mu * mu;
    float rstd = rsqrtf(var + 1e-5f);
    float* ob = out + (size_t)b * C * NP + p;
    for (int c = 0; c < C; c++) {
        float v = ib[(size_t)c * NP];
        ob[(size_t)c * NP] = (v - mu) * rstd * g[c] + be[c];
    }
}

// ---------------- unified GEMM: Y[o,p] = sum_k W[o,k] * Acat[k,p], + epilogue ----
// Acat rows: [0,K1) from A1, [K1,K) from A2.
// mode 0: Y = g
// mode 1: Y = g + E1[o,p]
// mode 2: base = (o<Chalf ? E1[o] : E2[o-Chalf]); Y = g*base + base
// mode 3: Y = gelu(E2[o,p]) * (g + E1[o,p])
#define BM 128
#define BN 128
#define BKK 8
__global__ void __launch_bounds__(256, 2)
gemm_kernel(const float* __restrict__ W, int K,
            const float* __restrict__ A1, int K1, int sA1,
            const float* __restrict__ A2, int sA2,
            int Cout,
            const float* __restrict__ E1, int sE1,
            const float* __restrict__ E2, int sE2,
            float* __restrict__ Y, int sY,
            int mode, int Chalf)
{
    __shared__ float As[BKK][BM];
    __shared__ float Bs[BKK][BN];
    int b  = blockIdx.z;
    int p0 = blockIdx.x * BN;
    int o0 = blockIdx.y * BM;
    const float* A1b = A1 + (size_t)b * sA1 * NP;
    const float* A2b = A2 ? A2 + (size_t)b * sA2 * NP : A1;
    int tid = threadIdx.x;
    int tx = tid & 15, ty = tid >> 4;

    float acc[8][8];
#pragma unroll
    for (int i = 0; i < 8; i++)
#pragma unroll
        for (int j = 0; j < 8; j++) acc[i][j] = 0.f;

    for (int k0 = 0; k0 < K; k0 += BKK) {
#pragma unroll
        for (int i = 0; i < 4; i++) {
            int e = tid + i * 256;
            int r = e >> 3, kk = e & 7;
            int o = o0 + r;
            As[kk][r] = (o < Cout) ? W[(size_t)o * K + k0 + kk] : 0.f;
        }
#pragma unroll
        for (int i = 0; i < 4; i++) {
            int e = tid + i * 256;
            int kk = e >> 7, pp = e & 127;
            int kg = k0 + kk;
            const float* src = (kg < K1) ? (A1b + (size_t)kg * NP)
                                         : (A2b + (size_t)(kg - K1) * NP);
            Bs[kk][pp] = src[p0 + pp];
        }
        __syncthreads();
#pragma unroll
        for (int kk = 0; kk < BKK; kk++) {
            float a[8], bb[8];
#pragma unroll
            for (int i = 0; i < 8; i++) a[i] = As[kk][ty * 8 + i];
#pragma unroll
            for (int j = 0; j < 8; j++) bb[j] = Bs[kk][tx * 8 + j];
#pragma unroll
            for (int i = 0; i < 8; i++)
#pragma unroll
                for (int j = 0; j < 8; j++)
                    acc[i][j] = fmaf(a[i], bb[j], acc[i][j]);
        }
        __syncthreads();
    }

    float* Yb = Y + (size_t)b * sY * NP;
    const float* E1b = E1 ? E1 + (size_t)b * sE1 * NP : nullptr;
    const float* E2b = E2 ? E2 + (size_t)b * sE2 * NP : nullptr;
#pragma unroll
    for (int i = 0; i < 8; i++) {
        int o = o0 + ty * 8 + i;
        if (o >= Cout) break;
#pragma unroll
        for (int j = 0; j < 8; j++) {
            int p = p0 + tx * 8 + j;
            float g = acc[i][j];
            float outv;
            if (mode == 0) {
                outv = g;
            } else if (mode == 1) {
                outv = g + E1b[(size_t)o * NP + p];
            } else if (mode == 2) {
                float base = (o < Chalf) ? E1b[(size_t)o * NP + p]
                                         : E2b[(size_t)(o - Chalf) * NP + p];
                outv = g * base + base;
            } else {
                float r  = g + E1b[(size_t)o * NP + p];
                float xg = E2b[(size_t)o * NP + p];
                float gel = 0.5f * xg * (1.f + erff(xg * 0.70710678118654752f));
                outv = gel * r;
            }
            Yb[(size_t)o * NP + p] = outv;
        }
    }
}

// ---------------- depthwise 3x3, SAME zero pad ----------------
__global__ void dw_kernel(const float* __restrict__ in, const float* __restrict__ w,
                          float* __restrict__ out, int C)
{
    int b = blockIdx.z, c = blockIdx.y;
    int p = blockIdx.x * 256 + threadIdx.x;
    int y = p >> 7, x = p & 127;
    const float* ib = in + ((size_t)b * C + c) * NP;
    const float* wc = w + c * 9;
    float acc = 0.f;
#pragma unroll
    for (int dy = -1; dy <= 1; dy++) {
        int yy = y + dy;
        if (yy < 0 || yy > 127) continue;
#pragma unroll
        for (int dx = -1; dx <= 1; dx++) {
            int xx = x + dx;
            if (xx < 0 || xx > 127) continue;
            acc = fmaf(ib[yy * 128 + xx], wc[(dy + 1) * 3 + (dx + 1)], acc);
        }
    }
    out[((size_t)b * C + c) * NP + p] = acc;
}

// ---------------- row L2 norms of q,k (channels 0..383 of QKV) ----------------
__global__ void norm_kernel(const float* __restrict__ qkv, float* __restrict__ nrm)
{
    int r = blockIdx.x;              // 0..767
    int b = r / 384, c = r % 384;
    const float* src = qkv + ((size_t)b * 576 + c) * NP;
    float s = 0.f;
    for (int i = threadIdx.x; i < NP; i += 256) {
        float v = src[i];
        s += v * v;
    }
    __shared__ float red[256];
    red[threadIdx.x] = s;
    __syncthreads();
    for (int st = 128; st > 0; st >>= 1) {
        if (threadIdx.x < st) red[threadIdx.x] += red[threadIdx.x + st];
        __syncthreads();
    }
    if (threadIdx.x == 0) nrm[r] = fmaxf(sqrtf(red[0]), 1e-12f);
}

// ---------------- attention scores: S_part[ks][bh][c][d] = sum_p q[c,p]k[d,p] ----
__global__ void scores_kernel(const float* __restrict__ qkv, float* __restrict__ S)
{
    int bh = blockIdx.x;             // 0..11
    int ks = blockIdx.y;             // 0..KSPLIT-1
    int b = bh / 6, h = bh % 6;
    const float* qb = qkv + ((size_t)b * 576 + h * 32) * NP;
    const float* kb = qkv + ((size_t)b * 576 + 192 + h * 32) * NP;
    __shared__ float qs[32][65], ksm[32][65];
    int tid = threadIdx.x;
    int c = tid >> 3, d0 = (tid & 7) * 4;
    float acc[4] = {0.f, 0.f, 0.f, 0.f};
    int kbase = ks * (NP / KSPLIT);
    for (int t = 0; t < (NP / KSPLIT) / 64; t++) {
        int k0 = kbase + t * 64;
#pragma unroll
        for (int i = 0; i < 8; i++) {
            int e = tid + i * 256;
            int row = e >> 6, col = e & 63;
            qs[row][col]  = qb[(size_t)row * NP + k0 + col];
            ksm[row][col] = kb[(size_t)row * NP + k0 + col];
        }
        __syncthreads();
#pragma unroll
        for (int kk = 0; kk < 64; kk++) {
            float qv = qs[c][kk];
#pragma unroll
            for (int j = 0; j < 4; j++)
                acc[j] = fmaf(qv, ksm[d0 + j][kk], acc[j]);
        }
        __syncthreads();
    }
    float* Sp = S + (size_t)ks * 12288 + bh * 1024 + c * 32 + d0;
#pragma unroll
    for (int j = 0; j < 4; j++) Sp[j] = acc[j];
}

// ---------------- softmax over d, with normalization + temperature ----------------
__global__ void softmax_kernel(float* __restrict__ S, const float* __restrict__ nrm,
                               const float* __restrict__ temp)
{
    int bh = blockIdx.y;             // 0..11
    int c  = blockIdx.x;             // 0..31
    int b = bh / 6, h = bh % 6;
    int d = threadIdx.x;             // 0..31
    float acc = 0.f;
    size_t idx = (size_t)bh * 1024 + c * 32 + d;
    for (int j = 0; j < KSPLIT; j++) acc += S[(size_t)j * 12288 + idx];
    float nq = nrm[b * 384 + h * 32 + c];
    float nk = nrm[b * 384 + 192 + h * 32 + d];
    float v = acc / (nq * nk) * temp[h];
    float m = v;
    for (int o = 16; o; o >>= 1) m = fmaxf(m, __shfl_xor_sync(0xffffffffu, m, o));
    float e = expf(v - m);
    float s = e;
    for (int o = 16; o; o >>= 1) s += __shfl_xor_sync(0xffffffffu, s, o);
    S[idx] = e / s;                  // store final attn into partial-0 slot
}

// ---------------- out = attn @ v ----------------
__global__ void av_kernel(const float* __restrict__ S, const float* __restrict__ qkv,
                          float* __restrict__ out)
{
    int b = blockIdx.z, h = blockIdx.y;
    int p = blockIdx.x * 128 + threadIdx.x;
    __shared__ float A[32][32];
    int bh = b * 6 + h;
    for (int i = threadIdx.x; i < 1024; i += 128)
        A[i >> 5][i & 31] = S[(size_t)bh * 1024 + i];
    __syncthreads();
    const float* vb = qkv + ((size_t)b * 576 + 384 + h * 32) * NP + p;
    float vr[32];
#pragma unroll
    for (int d = 0; d < 32; d++) vr[d] = vb[(size_t)d * NP];
    float* ob = out + ((size_t)b * 192 + h * 32) * NP + p;
#pragma unroll
    for (int c = 0; c < 32; c++) {
        float acc = 0.f;
#pragma unroll
        for (int d = 0; d < 32; d++) acc = fmaf(A[c][d], vr[d], acc);
        ob[(size_t)c * NP] = acc;
    }
}

// ---------------- host orchestration ----------------
static inline void launch_gemm(const float* W, int K,
                               const float* A1, int K1, int sA1,
                               const float* A2, int sA2,
                               int Cout,
                               const float* E1, int sE1,
                               const float* E2, int sE2,
                               float* Y, int sY, int mode, int Chalf)
{
    dim3 grid(NP / BN, (Cout + BM - 1) / BM, NB);
    gemm_kernel<<<grid, 256>>>(W, K, A1, K1, sA1, A2, sA2, Cout,
                               E1, sE1, E2, sE2, Y, sY, mode, Chalf);
}

extern "C" void kernel_launch(void* const* d_in, const int* in_sizes, int n_in,
                              void* d_out, int out_size)
{
    const float* x       = (const float*)d_in[0];
    const float* feature = (const float*)d_in[1];
    const float* nf_w = (const float*)d_in[2];
    const float* nf_b = (const float*)d_in[3];
    const float* n1_w = (const float*)d_in[4];
    const float* n1_b = (const float*)d_in[5];
    const float* n2_w = (const float*)d_in[6];
    const float* n2_b = (const float*)d_in[7];
    const float* a_cc_w   = (const float*)d_in[8];    // [384,384]
    const float* a_fus_w  = (const float*)d_in[9];    // [192,384]
    const float* a_msk_w  = (const float*)d_in[10];   // [192,192]
    const float* a_qkv_w  = (const float*)d_in[11];   // [576,192]
    const float* a_qkvdw  = (const float*)d_in[12];   // [576,1,3,3]
    const float* a_temp   = (const float*)d_in[13];   // [6]
    const float* a_proj_w = (const float*)d_in[14];   // [192,192]
    const float* f_pm_w   = (const float*)d_in[15];   // [576,192]
    const float* f_pi_w   = (const float*)d_in[16];   // [1152,192]
    const float* f_dw_w   = (const float*)d_in[17];   // [1152,1,3,3]
    const float* f_cc_w   = (const float*)d_in[18];   // [1152,1152]
    const float* f_fus_w  = (const float*)d_in[19];   // [576,1152]
    const float* f_msk_w  = (const float*)d_in[20];   // [576,576]
    const float* f_po_w   = (const float*)d_in[21];   // [192,576]
    float* out = (float*)d_out;

    float* base = nullptr;
    cudaGetSymbolAddress((void**)&base, g_scratch);
    float* F     = base + OFF_F;
    float* X1    = base + OFF_X1;
    float* MT    = base + OFF_MT;
    float* OUTD  = base + OFF_OUTD;
    float* ATTIN = base + OFF_ATTIN;
    float* QKV0  = base + OFF_QKV0;
    float* QKV   = base + OFF_QKV;
    float* OUTA  = base + OFF_OUTA;
    float* XMID  = base + OFF_XMID;
    float* X2L   = base + OFF_X2L;
    float* FM    = base + OFF_FM;
    float* XIN   = base + OFF_XIN;
    float* DW    = base + OFF_DW;
    float* MT2   = base + OFF_MT2;
    float* OUT2  = base + OFF_OUT2;
    float* GX    = base + OFF_GX;
    float* NRM   = base + OFF_NRM;
    float* S     = base + OFF_S;

    dim3 lng(NP / 256, NB);

    // feat = LN(feature); x1 = LN(x)
    ln_kernel<<<lng, 256>>>(feature, nf_w, nf_b, F, 192);
    ln_kernel<<<lng, 256>>>(x, n1_w, n1_b, X1, 192);

    // --- attention DDF ---
    launch_gemm(a_msk_w, 192, F, 192, 192, nullptr, 0, 192,
                nullptr, 0, nullptr, 0, MT, 192, 0, 0);
    launch_gemm(a_cc_w, 384, X1, 192, 192, MT, 192, 384,
                X1, 192, MT, 192, OUTD, 384, 2, 192);
    launch_gemm(a_fus_w, 384, OUTD, 384, 384, nullptr, 0, 192,
                X1, 192, nullptr, 0, ATTIN, 192, 1, 0);

    // qkv + depthwise
    launch_gemm(a_qkv_w, 192, ATTIN, 192, 192, nullptr, 0, 576,
                nullptr, 0, nullptr, 0, QKV0, 576, 0, 0);
    dw_kernel<<<dim3(NP / 256, 576, NB), 256>>>(QKV0, a_qkvdw, QKV, 576);

    // channel attention
    norm_kernel<<<768, 256>>>(QKV, NRM);
    scores_kernel<<<dim3(12, KSPLIT), 256>>>(QKV, S);
    softmax_kernel<<<dim3(32, 12), 32>>>(S, NRM, a_temp);
    av_kernel<<<dim3(NP / 128, 6, NB), 128>>>(S, QKV, OUTA);

    // proj + residual with original x
    launch_gemm(a_proj_w, 192, OUTA, 192, 192, nullptr, 0, 192,
                x, 192, nullptr, 0, XMID, 192, 1, 0);

    // --- FFN ---
    ln_kernel<<<lng, 256>>>(XMID, n2_w, n2_b, X2L, 192);
    launch_gemm(f_pm_w, 192, F, 192, 192, nullptr, 0, 576,
                nullptr, 0, nullptr, 0, FM, 576, 0, 0);
    launch_gemm(f_pi_w, 192, X2L, 192, 192, nullptr, 0, 1152,
                nullptr, 0, nullptr, 0, XIN, 1152, 0, 0);
    dw_kernel<<<dim3(NP / 256, 1152, NB), 256>>>(XIN, f_dw_w, DW, 1152);

    const float* X2H = DW + (size_t)576 * NP;   // second half of DW, batch-stride 1152
    launch_gemm(f_msk_w, 576, FM, 576, 576, nullptr, 0, 576,
                nullptr, 0, nullptr, 0, MT2, 576, 0, 0);
    launch_gemm(f_cc_w, 1152, X2H, 576, 1152, MT2, 576, 1152,
                X2H, 1152, MT2, 576, OUT2, 1152, 2, 576);
    // fused2 = fusion@OUT2 + X2H ; GX = gelu(X1H) * fused2
    launch_gemm(f_fus_w, 1152, OUT2, 1152, 1152, nullptr, 0, 576,
                X2H, 1152, DW, 1152, GX, 576, 3, 0);
    // out = XMID + projout@GX
    launch_gemm(f_po_w, 576, GX, 576, 576, nullptr, 0, 192,
                XMID, 192, nullptr, 0, out, 192, 1, 0);
}